// round 11
// baseline (speedup 1.0000x reference)
#include <cuda_runtime.h>
#include <cstdint>

#define B_   8
#define N_   64
#define NUM_CLASSES 81
#define C_   86
#define NLEV 5
#define NROWS 248
#define UNITS8_PER_B 43648                    // 8 slices x (HH/4) summed over levels
#define TOTAL_UNITS (B_ * UNITS8_PER_B)       // 349184
#define WBLK 128
#define WGRID (148 * 12)                      // 12 blocks/SM exactly

__constant__ int   c_H[NLEV]      = {128, 64, 32, 16, 8};
__constant__ int   c_logH[NLEV]   = {7, 6, 5, 4, 3};
__constant__ int   c_gshift4[NLEV]= {12, 10, 8, 6, 4};
__constant__ float c_ps[NLEV]     = {0.0078125f, 0.015625f, 0.03125f, 0.0625f, 0.125f};
__constant__ float c_invps[NLEV]  = {128.0f, 64.0f, 32.0f, 16.0f, 8.0f};
__constant__ float c_th0[NLEV]    = {0.0078125f, 0.0625f, 0.125f, 0.25f, 0.5f};
__constant__ float c_th1[NLEV]    = {0.0625f, 0.125f, 0.25f, 0.5f, 1.0f};
__constant__ size_t c_base[NLEV]  = {0ull, 11272192ull, 14090240ull, 14794752ull, 14970880ull};
__constant__ int   c_ubase[NLEV]  = {0, 32768, 40960, 43008, 43520};

// scratch (no allocation allowed)
__device__ float4             g_sboxes[B_][N_];
__device__ int                g_slabels[B_][N_];
__device__ unsigned long long g_cov[B_][NLEV][128][2];
__device__ unsigned long long g_cand[B_][NLEV][128];

// ---------------- K1: fused sort + per-row masks (validated R8-R10) ----------------
__global__ __launch_bounds__(256)
void prep_kernel(const float* __restrict__ boxes,
                 const int* __restrict__ labels) {
    const int b   = blockIdx.y;
    const int tid = threadIdx.x;
    __shared__ float  s_area[N_];
    __shared__ float4 s_sb[N_];
    __shared__ int    s_sl[N_];

    float4 w0;
    int lab0 = 0;
    if (tid < N_) {
        const float* bx = boxes + ((size_t)b * N_ + tid) * 4;
        w0 = make_float4(bx[0], bx[1], bx[2], bx[3]);
        lab0 = labels[(size_t)b * N_ + tid];
        s_area[tid] = (w0.z - w0.x) * (w0.w - w0.y);
    }
    __syncthreads();
    if (tid < N_) {
        float a = s_area[tid];
        int rank = 0;
#pragma unroll
        for (int j = 0; j < N_; j++) {
            float aj = s_area[j];
            rank += (aj > a) || (aj == a && j < tid);
        }
        s_sb[rank] = w0;
        s_sl[rank] = lab0;
    }
    __syncthreads();

    if (blockIdx.x == 0 && tid < N_) {
        g_sboxes[b][tid]  = s_sb[tid];
        g_slabels[b][tid] = s_sl[tid];
    }

    const int lane = tid & 31;
    const int rid  = blockIdx.x * 8 + (tid >> 5);
    if (rid >= NROWS) return;

    int lev, y;
    if      (rid < 128) { lev = 0; y = rid; }
    else if (rid < 192) { lev = 1; y = rid - 128; }
    else if (rid < 224) { lev = 2; y = rid - 192; }
    else if (rid < 240) { lev = 3; y = rid - 224; }
    else                { lev = 4; y = rid - 240; }

    const int   H     = c_H[lev];
    const float ps    = c_ps[lev];
    const float invps = c_invps[lev];
    const float t0m   = c_th0[lev] * 0.999f;
    const float t1m   = c_th1[lev] * 1.001f;
    const float my    = ((float)y + 0.5f) * ps;

    unsigned long long cv0 = 0ull, cv1 = 0ull, cand = 0ull;
#pragma unroll
    for (int t = 0; t < 2; t++) {
        const int n = lane + t * 32;
        float4 w = s_sb[n];
        if (my >= w.y && my <= w.w) {
            float md = fmaxf(w.z - w.x, w.w - w.y);
            if (md > t0m && 0.5f * md <= t1m) cand |= 1ull << n;

            int xlo = (int)ceilf(w.x * invps - 0.5f);
            if (((float)(xlo - 1) + 0.5f) * ps >= w.x) xlo--;
            else if (((float)xlo + 0.5f) * ps < w.x)  xlo++;
            int xhi = (int)floorf(w.z * invps - 0.5f);
            if (((float)(xhi + 1) + 0.5f) * ps <= w.z) xhi++;
            else if (((float)xhi + 0.5f) * ps > w.z)   xhi--;
            if (xlo < 0) xlo = 0;
            if (xhi > H - 1) xhi = H - 1;
            if (xlo <= xhi) {
                int l0 = xlo < 64 ? xlo : 64;
                int h0 = (xhi + 1) < 64 ? (xhi + 1) : 64;
                if (h0 > l0)
                    cv0 |= ((h0 == 64) ? ~0ull : ((1ull << h0) - 1)) & ~((1ull << l0) - 1);
                int l1 = xlo - 64 > 0 ? xlo - 64 : 0;
                int h1 = xhi + 1 - 64 > 0 ? xhi + 1 - 64 : 0;
                if (h1 > l1)
                    cv1 |= ((h1 == 64) ? ~0ull : ((1ull << h1) - 1)) & ~((1ull << l1) - 1);
            }
        }
    }
#pragma unroll
    for (int off = 16; off > 0; off >>= 1) {
        cv0  |= __shfl_xor_sync(0xFFFFFFFFu, cv0,  off);
        cv1  |= __shfl_xor_sync(0xFFFFFFFFu, cv1,  off);
        cand |= __shfl_xor_sync(0xFFFFFFFFu, cand, off);
    }
    if (lane == 0) {
        g_cov[b][lev][y][0] = cv0;
        g_cov[b][lev][y][1] = cv1;
        g_cand[b][lev][y]   = cand;
    }
}

// ---------------- unit worker ----------------
__device__ __forceinline__ void do_unit(float* __restrict__ out, int u) {
    const int b   = u / UNITS8_PER_B;
    const int r   = u - b * UNITS8_PER_B;
    const int lev = r < 32768 ? 0 : r < 40960 ? 1 : r < 43008 ? 2 : r < 43520 ? 3 : 4;
    const int local = r - c_ubase[lev];
    const int gsh   = c_gshift4[lev];
    const int s = local >> gsh;                        // slice 0..7
    const int g = local & ((1 << gsh) - 1);

    const int H  = c_H[lev];
    const int HH = H * H;
    const int gx4 = g << 2;
    const int y   = gx4 >> c_logH[lev];
    const int x0  = gx4 & (H - 1);

    // metadata loads first (independent of the zero stores)
    unsigned long long cand = g_cand[b][lev][y];
    const unsigned long long cov = (s == 0) ? g_cov[b][lev][y][x0 >> 6] : 0ull;

    float* rowp = out + c_base[lev] + (size_t)b * C_ * HH + (size_t)y * H + x0;
    const size_t cs = (size_t)HH;
    float* clsp = rowp + 5 * cs;
    const float4 z = make_float4(0.0f, 0.0f, 0.0f, 0.0f);

    // ---- phase 1: zero channels [11s, min(11s+11,86)) ----
    float* slicep = rowp + (size_t)(11 * s) * cs;
    if (s == 7) {
#pragma unroll 9
        for (int i = 0; i < 9; i++)
            *reinterpret_cast<float4*>(slicep + (size_t)i * cs) = z;
    } else {
#pragma unroll 11
        for (int i = 0; i < 11; i++)
            *reinterpret_cast<float4*>(slicep + (size_t)i * cs) = z;
    }

    // ---- phase 2: sparse values / patches ----
    const int sh = x0 & 63;
    if (cand == 0ull) {
        if (s == 0) {
#pragma unroll
            for (int k = 0; k < 4; k++)
                if (!((cov >> (sh + k)) & 1ull)) clsp[k] = 1.0f;   // background
        }
        return;
    }

    const float ps  = c_ps[lev];
    const float th0 = c_th0[lev];
    const float th1 = c_th1[lev];
    const float my = ((float)y + 0.5f) * ps;
    float mx[4];
#pragma unroll
    for (int k = 0; k < 4; k++) mx[k] = ((float)(x0 + k) + 0.5f) * ps;

    int win[4] = {-1, -1, -1, -1};
    while (cand) {
        const int n = __ffsll(cand) - 1;
        cand &= cand - 1;
        float4 w = g_sboxes[b][n];
        float t   = my - w.y;
        float bo  = w.w - my;
        float tbx = fmaxf(t, bo);
#pragma unroll
        for (int k = 0; k < 4; k++) {
            float l = mx[k] - w.x, rr = w.z - mx[k];
            float mxv = fmaxf(fmaxf(l, rr), tbx);
            if (fminf(l, rr) >= 0.0f && mxv > th0 && mxv <= th1) win[k] = n;
        }
    }

    if (s == 0) {
        // per-pixel scalar overwrites (same thread zeroed ch0-10 above)
#pragma unroll
        for (int k = 0; k < 4; k++) {
            if (win[k] >= 0) {
                float4 w = g_sboxes[b][win[k]];
                float l  = mx[k] - w.x;
                float t  = my    - w.y;
                float rr = w.z - mx[k];
                float bo = w.w - my;
                rowp[0 * cs + k] = l;
                rowp[1 * cs + k] = t;
                rowp[2 * cs + k] = rr;
                rowp[3 * cs + k] = bo;
                float dx = fminf(l, rr),  Dx = fmaxf(l, rr);
                float dy = fminf(t, bo),  Dy = fmaxf(t, bo);
                float arg = (dx / (Dx != 0.0f ? Dx : 1.0f)) *
                            (dy / (Dy != 0.0f ? Dy : 1.0f));
                rowp[4 * cs + k] = (arg > 0.0f) ? sqrtf(arg) : 0.0f;
                int lab = g_slabels[b][win[k]];
                if (lab < 6) clsp[(size_t)lab * cs + k] = 1.0f;    // cls 0..5 in slice 0
            } else if (!((cov >> (sh + k)) & 1ull)) {
                clsp[k] = 1.0f;
            }
        }
    } else {
        const int lo = 11 * s - 5;                                  // cls range of slice
        const int hi = (s == 7) ? NUM_CLASSES : lo + 11;
#pragma unroll
        for (int k = 0; k < 4; k++) {
            if (win[k] >= 0) {
                int lab = g_slabels[b][win[k]];
                if (lab >= lo && lab < hi) clsp[(size_t)lab * cs + k] = 1.0f;
            }
        }
    }
}

// ---------------- K2: grid-stride writer, high occupancy ----------------
__global__ __launch_bounds__(WBLK, 12)
void fused_kernel(float* __restrict__ out) {
    for (int u = blockIdx.x * WBLK + threadIdx.x; u < TOTAL_UNITS; u += WGRID * WBLK)
        do_unit(out, u);
}

extern "C" void kernel_launch(void* const* d_in, const int* in_sizes, int n_in,
                              void* d_out, int out_size) {
    const float* boxes  = (const float*)d_in[0];
    const int*   labels = (const int*)d_in[1];
    float* out = (float*)d_out;

    dim3 pgrid(31, B_);
    prep_kernel<<<pgrid, 256>>>(boxes, labels);

    fused_kernel<<<WGRID, WBLK>>>(out);
}